// round 13
// baseline (speedup 1.0000x reference)
#include <cuda_runtime.h>
#include <cstdint>

#define BATCH 16
#define NA    25200
#define NC    80
#define TOPK  2048
#define NMS_T 0.45f
#define CONF_T 0.25f
#define FULLM 0xffffffffu

// ---------------- scratch (__device__ globals; zero-initialized at load) ----------------
__device__ float              g_scores[BATCH * NA];          // conf-filtered max score
__device__ int                g_labels[BATCH * NA];          // argmax class
__device__ float              g_topboxes[BATCH * TOPK * 4];  // gathered boxes (xyxy)
__device__ float              g_topscore[BATCH * TOPK];
__device__ int                g_topidx[BATCH * TOPK];
__device__ __align__(16) unsigned long long g_mask[(size_t)BATCH * TOPK * 32]; // 8MB bit-matrix
__device__ unsigned char      g_keep[BATCH * TOPK];

// ---------------- K1: score = max_c(obj*cp), label = first-argmax ----------------
__global__ void k_scores(const float* __restrict__ obj, const float* __restrict__ cls) {
    int g = blockIdx.x * blockDim.x + threadIdx.x;
    if (g >= BATCH * NA) return;
    float o = obj[g];
    const float4* cp = reinterpret_cast<const float4*>(cls) + (size_t)g * (NC / 4);
    float best = -1.0f; int bi = 0;
#pragma unroll
    for (int q = 0; q < NC / 4; ++q) {
        float4 v = cp[q];
        float p;
        p = o * v.x; if (p > best) { best = p; bi = 4 * q + 0; }
        p = o * v.y; if (p > best) { best = p; bi = 4 * q + 1; }
        p = o * v.z; if (p > best) { best = p; bi = 4 * q + 2; }
        p = o * v.w; if (p > best) { best = p; bi = 4 * q + 3; }
    }
    g_scores[g] = (best > CONF_T) ? best : 0.0f;
    g_labels[g] = bi;
}

// ---------------- K2: per-image exact top-2048 (sorted desc, tie -> low idx) ----------------
// composite key: (float_bits(score) << 15) | (32767 - idx)   -- 48 bits, all distinct
// 4-pass 12-bit radix select with warp-parallel 3-level digit search.
__global__ void k_topk(const float* __restrict__ boxes) {
    const int b = blockIdx.x;
    const int t = threadIdx.x;                 // 1024 threads
    const float* __restrict__ sc = g_scores + (size_t)b * NA;

    __shared__ unsigned int hist[4096];
    __shared__ unsigned long long keys[TOPK];
    __shared__ unsigned long long sh_prefix;
    __shared__ int sh_rem;
    __shared__ unsigned int sh_cnt;

    if (t == 0) { sh_prefix = 0ull; sh_rem = TOPK; sh_cnt = 0u; }
    for (int i = t; i < TOPK; i += 1024) keys[i] = 0ull;
    __syncthreads();

    for (int shift = 36; shift >= 0; shift -= 12) {
        for (int i = t; i < 4096; i += 1024) hist[i] = 0u;
        __syncthreads();
        unsigned long long prefix = sh_prefix;
        for (int n = t; n < NA; n += 1024) {
            unsigned long long key =
                ((unsigned long long)__float_as_uint(sc[n]) << 15) |
                (unsigned long long)(32767 - n);
            if ((key >> (shift + 12)) == prefix)
                atomicAdd(&hist[(unsigned)(key >> shift) & 4095u], 1u);
        }
        __syncthreads();
        if (t < 32) {                              // warp 0: parallel digit search
            const int lane = t;
            unsigned rem = (unsigned)sh_rem;
            // --- level 1: lane covers 128 bins ---
            unsigned a0 = 0, a1 = 0, a2 = 0, a3 = 0;
            int base1 = lane * 128;
            for (int i = 0; i < 128; i += 4) {
                a0 += hist[base1 + i + 0]; a1 += hist[base1 + i + 1];
                a2 += hist[base1 + i + 2]; a3 += hist[base1 + i + 3];
            }
            unsigned c1 = a0 + a1 + a2 + a3;
            unsigned v = c1;                       // inclusive suffix sum over lanes
            for (int o = 1; o < 32; o <<= 1) {
                unsigned u = __shfl_down_sync(FULLM, v, o);
                if (lane + o < 32) v += u;
            }
            unsigned sufex = v - c1;
            unsigned bal = __ballot_sync(FULLM, (sufex < rem) && (rem <= v));
            int L1 = __ffs(bal) - 1;
            rem -= __shfl_sync(FULLM, sufex, L1);
            // --- level 2: 4 bins per lane inside region L1 ---
            int base2 = L1 * 128 + lane * 4;
            unsigned c2 = hist[base2] + hist[base2 + 1] + hist[base2 + 2] + hist[base2 + 3];
            v = c2;
            for (int o = 1; o < 32; o <<= 1) {
                unsigned u = __shfl_down_sync(FULLM, v, o);
                if (lane + o < 32) v += u;
            }
            sufex = v - c2;
            bal = __ballot_sync(FULLM, (sufex < rem) && (rem <= v));
            int L2 = __ffs(bal) - 1;
            rem -= __shfl_sync(FULLM, sufex, L2);
            // --- level 3: serial over 4 bins (high digit first) ---
            if (lane == L2) {
                int b3 = L1 * 128 + L2 * 4;
                unsigned cum = 0; int d = 3;
                for (d = 3; d >= 0; --d) {
                    unsigned h = hist[b3 + d];
                    if (cum + h >= rem) break;
                    cum += h;
                }
                sh_prefix = (prefix << 12) | (unsigned long long)(unsigned)(b3 + d);
                sh_rem = (int)(rem - cum);
            }
        }
        __syncthreads();
    }
    const unsigned long long T = sh_prefix;    // exact K-th largest key

    // collect all keys >= T (exactly TOPK, keys are distinct)
    for (int n = t; n < NA; n += 1024) {
        unsigned long long key =
            ((unsigned long long)__float_as_uint(sc[n]) << 15) |
            (unsigned long long)(32767 - n);
        if (key >= T) {
            unsigned p = atomicAdd(&sh_cnt, 1u);
            if (p < TOPK) keys[p] = key;
        }
    }
    __syncthreads();

    // bitonic sort descending (2048 elems, 1024 threads)
    for (int kk = 2; kk <= TOPK; kk <<= 1) {
        for (int j = kk >> 1; j > 0; j >>= 1) {
            for (int i = t; i < TOPK; i += 1024) {
                int l = i ^ j;
                if (l > i) {
                    bool dir = ((i & kk) == 0);  // true -> descending
                    unsigned long long a = keys[i], c = keys[l];
                    if ((a < c) == dir) { keys[i] = c; keys[l] = a; }
                }
            }
            __syncthreads();
        }
    }

    // emit sorted top-K: score, idx, gathered box
    for (int r = t; r < TOPK; r += 1024) {
        unsigned long long key = keys[r];
        int idx = 32767 - (int)(key & 0x7FFFull);
        float score = __uint_as_float((unsigned)(key >> 15));
        int o = b * TOPK + r;
        g_topidx[o] = idx;
        g_topscore[o] = score;
        float4 bx = reinterpret_cast<const float4*>(boxes)[(size_t)b * NA + idx];
        reinterpret_cast<float4*>(g_topboxes)[o] = bx;
    }
}

// ---------------- K3: 64x64 suppression bit-tiles (upper triangle only) ----------------
__global__ void k_mask() {
    if (blockIdx.x < blockIdx.y) return;   // col block strictly left of row block -> all zero
    const int b = blockIdx.z;
    const int rowblk = blockIdx.y, colblk = blockIdx.x;
    const int t = threadIdx.x;             // 64 threads
    __shared__ float4 colbox[64];

    const int col0 = colblk * 64;
    colbox[t] = reinterpret_cast<const float4*>(g_topboxes)[b * TOPK + col0 + t];
    __syncthreads();

    const int row = rowblk * 64 + t;
    float4 rb = reinterpret_cast<const float4*>(g_topboxes)[b * TOPK + row];
    float area1 = (rb.z - rb.x) * (rb.w - rb.y);

    unsigned long long bits = 0ull;
#pragma unroll 4
    for (int j = 0; j < 64; ++j) {
        int col = col0 + j;
        if (col > row) {
            float4 c = colbox[j];
            float area2 = (c.z - c.x) * (c.w - c.y);
            float lx = fmaxf(rb.x, c.x), ly = fmaxf(rb.y, c.y);
            float rx = fminf(rb.z, c.z), ry = fminf(rb.w, c.w);
            float w = fmaxf(rx - lx, 0.0f), h = fmaxf(ry - ly, 0.0f);
            float inter = w * h;
            bool sup = false;
            if (inter > 0.0f) {
                float un = area1 + area2 - inter;
                sup = (__fdiv_rn(inter, un) > NMS_T);   // IEEE div: matches XLA div.rn
            }
            if (sup) bits |= (1ull << j);
        }
    }
    g_mask[((size_t)b * TOPK + row) * 32 + colblk] = bits;
}

// ---------------- K4: chunked greedy reduce, cp.async-staged (one warp per image) ----------------
// 64 chunks of 32 rows. Each chunk is a contiguous 8KB gmem block, staged into a
// 4-slot smem ring with 3-deep cp.async prefetch. Diagonal 32x32 block is read
// via broadcast smem loads; the serial greedy chain is branch-free SHF+SHF+LOP3.

__device__ __forceinline__ void cp_async16(uint32_t saddr, const void* gptr) {
    asm volatile("cp.async.cg.shared.global [%0], [%1], 16;" :: "r"(saddr), "l"(gptr));
}

__device__ __forceinline__ void stage_chunk(const unsigned long long* __restrict__ Mc,
                                            unsigned long long* slot, int lane) {
    uint32_t s = (uint32_t)__cvta_generic_to_shared(slot) + lane * 16;
    const char* g = (const char*)Mc + lane * 16;
#pragma unroll
    for (int k = 0; k < 16; ++k)
        cp_async16(s + k * 512, g + k * 512);
    asm volatile("cp.async.commit_group;");
}

__global__ void __launch_bounds__(32, 1) k_reduce() {
    const int b = blockIdx.x;
    const int lane = threadIdx.x;          // lane owns column word `lane` (cols lane*64..+63)

    __shared__ __align__(16) unsigned long long ring[4][1024];   // 32 KB

    const unsigned long long* __restrict__ M = g_mask + (size_t)b * TOPK * 32;

    // prefetch chunks 0..2
    stage_chunk(M + 0 * 1024, ring[0], lane);
    stage_chunk(M + 1 * 1024, ring[1], lane);
    stage_chunk(M + 2 * 1024, ring[2], lane);

    // build keep0 bits for this lane's 64 columns (overlaps with cp.async latency)
    unsigned long long keep0w = 0ull;
    const float* ts = g_topscore + b * TOPK;
#pragma unroll 8
    for (int q = 0; q < 64; ++q)
        if (ts[lane * 64 + q] > 0.0f) keep0w |= (1ull << q);

    unsigned char* __restrict__ keepout = g_keep + b * TOPK;
    unsigned long long removed = 0ull;

    for (int c = 0; c < 64; ++c) {
        asm volatile("cp.async.wait_group 2;");   // chunk c resident
        __syncwarp();

        const unsigned long long* rowp = ring[c & 3];
        const int owner = c >> 1;
        const int sh = (c & 1) * 32;

        // diagonal 32x32 block: broadcast smem loads (all lanes same address)
        unsigned d[32];
#pragma unroll
        for (int i = 0; i < 32; ++i)
            d[i] = (unsigned)(rowp[i * 32 + owner] >> sh);

        unsigned long long av64 = __shfl_sync(FULLM, keep0w & ~removed, owner);
        unsigned alive = (unsigned)(av64 >> sh);

        // branch-free serial greedy: SHF + SHF(arith) + LOP3 per bit
#pragma unroll
        for (int i = 0; i < 32; ++i)
            alive &= ~(d[i] & (unsigned)((int)(alive << (31 - i)) >> 31));

        // parallel OR of alive rows into this lane's removed word
#pragma unroll
        for (int i = 0; i < 32; ++i)
            if ((alive >> i) & 1u) removed |= rowp[i * 32 + lane];

        keepout[c * 32 + lane] = (unsigned char)((alive >> lane) & 1u);

        // keep exactly 3 groups in flight (wrap harmlessly reloads early chunks
        // into slots already consumed)
        stage_chunk(M + (size_t)((c + 3) & 63) * 1024, ring[(c + 3) & 3], lane);
    }
}

// ---------------- K5: finalize outputs [boxes | scores | labels] as float32 ----------------
__global__ void k_final(float* __restrict__ out) {
    int g = blockIdx.x * blockDim.x + threadIdx.x;    // B*TOPK
    if (g >= BATCH * TOPK) return;
    int b = g >> 11;
    bool k = g_keep[g] != 0;
    float m = k ? 1.0f : 0.0f;
    float4 bx = reinterpret_cast<const float4*>(g_topboxes)[g];
    float4 o = make_float4(bx.x * m, bx.y * m, bx.z * m, bx.w * m);
    reinterpret_cast<float4*>(out)[g] = o;                         // boxes region
    out[BATCH * TOPK * 4 + g] = k ? g_topscore[g] : 0.0f;          // scores region
    int lab = g_labels[(size_t)b * NA + g_topidx[g]];
    out[BATCH * TOPK * 5 + g] = k ? (float)lab : 0.0f;             // labels region
}

// ---------------- launch ----------------
extern "C" void kernel_launch(void* const* d_in, const int* in_sizes, int n_in,
                              void* d_out, int out_size) {
    const float* boxes = (const float*)d_in[0];   // [16,25200,4]
    const float* obj   = (const float*)d_in[1];   // [16,25200]
    const float* cls   = (const float*)d_in[2];   // [16,25200,80]
    float* out = (float*)d_out;

    k_scores<<<(BATCH * NA + 255) / 256, 256>>>(obj, cls);
    k_topk<<<BATCH, 1024>>>(boxes);
    dim3 g3(32, 32, BATCH);
    k_mask<<<g3, 64>>>();
    k_reduce<<<BATCH, 32>>>();
    k_final<<<(BATCH * TOPK + 255) / 256, 256>>>(out);
}

// round 14
// speedup vs baseline: 1.0020x; 1.0020x over previous
#include <cuda_runtime.h>
#include <cstdint>

#define BATCH 16
#define NA    25200
#define NC    80
#define TOPK  2048
#define NMS_T 0.45f
#define CONF_T 0.25f
#define FULLM 0xffffffffu

// ---------------- scratch (__device__ globals; zero-initialized at load) ----------------
__device__ float              g_scores[BATCH * NA];          // conf-filtered max score
__device__ int                g_labels[BATCH * NA];          // argmax class
__device__ float              g_topboxes[BATCH * TOPK * 4];  // gathered boxes (xyxy)
__device__ float              g_topscore[BATCH * TOPK];
__device__ int                g_topidx[BATCH * TOPK];
__device__ __align__(16) unsigned long long g_mask[(size_t)BATCH * TOPK * 32]; // 8MB bit-matrix
__device__ unsigned char      g_keep[BATCH * TOPK];

// ---------------- K1: score = max_c(obj*cp), label = first-argmax ----------------
__global__ void k_scores(const float* __restrict__ obj, const float* __restrict__ cls) {
    int g = blockIdx.x * blockDim.x + threadIdx.x;
    if (g >= BATCH * NA) return;
    float o = obj[g];
    const float4* cp = reinterpret_cast<const float4*>(cls) + (size_t)g * (NC / 4);
    float best = -1.0f; int bi = 0;
#pragma unroll
    for (int q = 0; q < NC / 4; ++q) {
        float4 v = cp[q];
        float p;
        p = o * v.x; if (p > best) { best = p; bi = 4 * q + 0; }
        p = o * v.y; if (p > best) { best = p; bi = 4 * q + 1; }
        p = o * v.z; if (p > best) { best = p; bi = 4 * q + 2; }
        p = o * v.w; if (p > best) { best = p; bi = 4 * q + 3; }
    }
    g_scores[g] = (best > CONF_T) ? best : 0.0f;
    g_labels[g] = bi;
}

// ---------------- K2: per-image exact top-2048 (sorted desc, tie -> low idx) ----------------
// composite key: (float_bits(score) << 15) | (32767 - idx)   -- 48 bits, all distinct
// 4-pass 12-bit radix select with warp-parallel 3-level digit search.
__global__ void k_topk(const float* __restrict__ boxes) {
    const int b = blockIdx.x;
    const int t = threadIdx.x;                 // 1024 threads
    const float* __restrict__ sc = g_scores + (size_t)b * NA;

    __shared__ unsigned int hist[4096];
    __shared__ unsigned long long keys[TOPK];
    __shared__ unsigned long long sh_prefix;
    __shared__ int sh_rem;
    __shared__ unsigned int sh_cnt;

    if (t == 0) { sh_prefix = 0ull; sh_rem = TOPK; sh_cnt = 0u; }
    for (int i = t; i < TOPK; i += 1024) keys[i] = 0ull;
    __syncthreads();

    for (int shift = 36; shift >= 0; shift -= 12) {
        for (int i = t; i < 4096; i += 1024) hist[i] = 0u;
        __syncthreads();
        unsigned long long prefix = sh_prefix;
        for (int n = t; n < NA; n += 1024) {
            unsigned long long key =
                ((unsigned long long)__float_as_uint(sc[n]) << 15) |
                (unsigned long long)(32767 - n);
            if ((key >> (shift + 12)) == prefix)
                atomicAdd(&hist[(unsigned)(key >> shift) & 4095u], 1u);
        }
        __syncthreads();
        if (t < 32) {                              // warp 0: parallel digit search
            const int lane = t;
            unsigned rem = (unsigned)sh_rem;
            // --- level 1: lane covers 128 bins ---
            unsigned a0 = 0, a1 = 0, a2 = 0, a3 = 0;
            int base1 = lane * 128;
            for (int i = 0; i < 128; i += 4) {
                a0 += hist[base1 + i + 0]; a1 += hist[base1 + i + 1];
                a2 += hist[base1 + i + 2]; a3 += hist[base1 + i + 3];
            }
            unsigned c1 = a0 + a1 + a2 + a3;
            unsigned v = c1;                       // inclusive suffix sum over lanes
            for (int o = 1; o < 32; o <<= 1) {
                unsigned u = __shfl_down_sync(FULLM, v, o);
                if (lane + o < 32) v += u;
            }
            unsigned sufex = v - c1;
            unsigned bal = __ballot_sync(FULLM, (sufex < rem) && (rem <= v));
            int L1 = __ffs(bal) - 1;
            rem -= __shfl_sync(FULLM, sufex, L1);
            // --- level 2: 4 bins per lane inside region L1 ---
            int base2 = L1 * 128 + lane * 4;
            unsigned c2 = hist[base2] + hist[base2 + 1] + hist[base2 + 2] + hist[base2 + 3];
            v = c2;
            for (int o = 1; o < 32; o <<= 1) {
                unsigned u = __shfl_down_sync(FULLM, v, o);
                if (lane + o < 32) v += u;
            }
            sufex = v - c2;
            bal = __ballot_sync(FULLM, (sufex < rem) && (rem <= v));
            int L2 = __ffs(bal) - 1;
            rem -= __shfl_sync(FULLM, sufex, L2);
            // --- level 3: serial over 4 bins (high digit first) ---
            if (lane == L2) {
                int b3 = L1 * 128 + L2 * 4;
                unsigned cum = 0; int d = 3;
                for (d = 3; d >= 0; --d) {
                    unsigned h = hist[b3 + d];
                    if (cum + h >= rem) break;
                    cum += h;
                }
                sh_prefix = (prefix << 12) | (unsigned long long)(unsigned)(b3 + d);
                sh_rem = (int)(rem - cum);
            }
        }
        __syncthreads();
    }
    const unsigned long long T = sh_prefix;    // exact K-th largest key

    // collect all keys >= T (exactly TOPK, keys are distinct)
    for (int n = t; n < NA; n += 1024) {
        unsigned long long key =
            ((unsigned long long)__float_as_uint(sc[n]) << 15) |
            (unsigned long long)(32767 - n);
        if (key >= T) {
            unsigned p = atomicAdd(&sh_cnt, 1u);
            if (p < TOPK) keys[p] = key;
        }
    }
    __syncthreads();

    // bitonic sort descending (2048 elems, 1024 threads)
    for (int kk = 2; kk <= TOPK; kk <<= 1) {
        for (int j = kk >> 1; j > 0; j >>= 1) {
            for (int i = t; i < TOPK; i += 1024) {
                int l = i ^ j;
                if (l > i) {
                    bool dir = ((i & kk) == 0);  // true -> descending
                    unsigned long long a = keys[i], c = keys[l];
                    if ((a < c) == dir) { keys[i] = c; keys[l] = a; }
                }
            }
            __syncthreads();
        }
    }

    // emit sorted top-K: score, idx, gathered box
    for (int r = t; r < TOPK; r += 1024) {
        unsigned long long key = keys[r];
        int idx = 32767 - (int)(key & 0x7FFFull);
        float score = __uint_as_float((unsigned)(key >> 15));
        int o = b * TOPK + r;
        g_topidx[o] = idx;
        g_topscore[o] = score;
        float4 bx = reinterpret_cast<const float4*>(boxes)[(size_t)b * NA + idx];
        reinterpret_cast<float4*>(g_topboxes)[o] = bx;
    }
}

// ---------------- K3: 64x64 suppression bit-tiles (upper triangle only) ----------------
__global__ void k_mask() {
    if (blockIdx.x < blockIdx.y) return;   // col block strictly left of row block -> all zero
    const int b = blockIdx.z;
    const int rowblk = blockIdx.y, colblk = blockIdx.x;
    const int t = threadIdx.x;             // 64 threads
    __shared__ float4 colbox[64];

    const int col0 = colblk * 64;
    colbox[t] = reinterpret_cast<const float4*>(g_topboxes)[b * TOPK + col0 + t];
    __syncthreads();

    const int row = rowblk * 64 + t;
    float4 rb = reinterpret_cast<const float4*>(g_topboxes)[b * TOPK + row];
    float area1 = (rb.z - rb.x) * (rb.w - rb.y);

    unsigned long long bits = 0ull;
#pragma unroll 4
    for (int j = 0; j < 64; ++j) {
        int col = col0 + j;
        if (col > row) {
            float4 c = colbox[j];
            float area2 = (c.z - c.x) * (c.w - c.y);
            float lx = fmaxf(rb.x, c.x), ly = fmaxf(rb.y, c.y);
            float rx = fminf(rb.z, c.z), ry = fminf(rb.w, c.w);
            float w = fmaxf(rx - lx, 0.0f), h = fmaxf(ry - ly, 0.0f);
            float inter = w * h;
            bool sup = false;
            if (inter > 0.0f) {
                float un = area1 + area2 - inter;
                sup = (__fdiv_rn(inter, un) > NMS_T);   // IEEE div: matches XLA div.rn
            }
            if (sup) bits |= (1ull << j);
        }
    }
    g_mask[((size_t)b * TOPK + row) * 32 + colblk] = bits;
}

// ---------------- K4: chunked greedy reduce, cp.async-staged (one warp per image) ----------------
// 64 chunks of 32 rows. Each chunk is a contiguous 8KB gmem block, staged into a
// 4-slot smem ring with 3-deep cp.async prefetch. Diagonal 32x32 block is read
// via broadcast smem loads; the serial greedy chain is branch-free SHF+SHF+LOP3.

__device__ __forceinline__ void cp_async16(uint32_t saddr, const void* gptr) {
    asm volatile("cp.async.cg.shared.global [%0], [%1], 16;" :: "r"(saddr), "l"(gptr));
}

__device__ __forceinline__ void stage_chunk(const unsigned long long* __restrict__ Mc,
                                            unsigned long long* slot, int lane) {
    uint32_t s = (uint32_t)__cvta_generic_to_shared(slot) + lane * 16;
    const char* g = (const char*)Mc + lane * 16;
#pragma unroll
    for (int k = 0; k < 16; ++k)
        cp_async16(s + k * 512, g + k * 512);
    asm volatile("cp.async.commit_group;");
}

__global__ void __launch_bounds__(32, 1) k_reduce() {
    const int b = blockIdx.x;
    const int lane = threadIdx.x;          // lane owns column word `lane` (cols lane*64..+63)

    __shared__ __align__(16) unsigned long long ring[4][1024];   // 32 KB

    const unsigned long long* __restrict__ M = g_mask + (size_t)b * TOPK * 32;

    // prefetch chunks 0..2
    stage_chunk(M + 0 * 1024, ring[0], lane);
    stage_chunk(M + 1 * 1024, ring[1], lane);
    stage_chunk(M + 2 * 1024, ring[2], lane);

    // build keep0 bits for this lane's 64 columns (overlaps with cp.async latency)
    unsigned long long keep0w = 0ull;
    const float* ts = g_topscore + b * TOPK;
#pragma unroll 8
    for (int q = 0; q < 64; ++q)
        if (ts[lane * 64 + q] > 0.0f) keep0w |= (1ull << q);

    unsigned char* __restrict__ keepout = g_keep + b * TOPK;
    unsigned long long removed = 0ull;

    for (int c = 0; c < 64; ++c) {
        asm volatile("cp.async.wait_group 2;");   // chunk c resident
        __syncwarp();

        const unsigned long long* rowp = ring[c & 3];
        const int owner = c >> 1;
        const int sh = (c & 1) * 32;

        // diagonal 32x32 block: broadcast smem loads (all lanes same address)
        unsigned d[32];
#pragma unroll
        for (int i = 0; i < 32; ++i)
            d[i] = (unsigned)(rowp[i * 32 + owner] >> sh);

        unsigned long long av64 = __shfl_sync(FULLM, keep0w & ~removed, owner);
        unsigned alive = (unsigned)(av64 >> sh);

        // branch-free serial greedy: SHF + SHF(arith) + LOP3 per bit
#pragma unroll
        for (int i = 0; i < 32; ++i)
            alive &= ~(d[i] & (unsigned)((int)(alive << (31 - i)) >> 31));

        // parallel OR of alive rows into this lane's removed word
#pragma unroll
        for (int i = 0; i < 32; ++i)
            if ((alive >> i) & 1u) removed |= rowp[i * 32 + lane];

        keepout[c * 32 + lane] = (unsigned char)((alive >> lane) & 1u);

        // keep exactly 3 groups in flight (wrap harmlessly reloads early chunks
        // into slots already consumed)
        stage_chunk(M + (size_t)((c + 3) & 63) * 1024, ring[(c + 3) & 3], lane);
    }
}

// ---------------- K5: finalize outputs [boxes | scores | labels] as float32 ----------------
__global__ void k_final(float* __restrict__ out) {
    int g = blockIdx.x * blockDim.x + threadIdx.x;    // B*TOPK
    if (g >= BATCH * TOPK) return;
    int b = g >> 11;
    bool k = g_keep[g] != 0;
    float m = k ? 1.0f : 0.0f;
    float4 bx = reinterpret_cast<const float4*>(g_topboxes)[g];
    float4 o = make_float4(bx.x * m, bx.y * m, bx.z * m, bx.w * m);
    reinterpret_cast<float4*>(out)[g] = o;                         // boxes region
    out[BATCH * TOPK * 4 + g] = k ? g_topscore[g] : 0.0f;          // scores region
    int lab = g_labels[(size_t)b * NA + g_topidx[g]];
    out[BATCH * TOPK * 5 + g] = k ? (float)lab : 0.0f;             // labels region
}

// ---------------- launch ----------------
extern "C" void kernel_launch(void* const* d_in, const int* in_sizes, int n_in,
                              void* d_out, int out_size) {
    const float* boxes = (const float*)d_in[0];   // [16,25200,4]
    const float* obj   = (const float*)d_in[1];   // [16,25200]
    const float* cls   = (const float*)d_in[2];   // [16,25200,80]
    float* out = (float*)d_out;

    k_scores<<<(BATCH * NA + 255) / 256, 256>>>(obj, cls);
    k_topk<<<BATCH, 1024>>>(boxes);
    dim3 g3(32, 32, BATCH);
    k_mask<<<g3, 64>>>();
    k_reduce<<<BATCH, 32>>>();
    k_final<<<(BATCH * TOPK + 255) / 256, 256>>>(out);
}